// round 3
// baseline (speedup 1.0000x reference)
#include <cuda_runtime.h>
#include <math.h>

#define D 128
#define NMAX 50000
#define EMAX 800000
#define GPAD 136   // smem row pad (floats): conflict-free B-frag loads

// Scratch (device globals — no allocation allowed)
__device__ float g_xw[(size_t)NMAX * D];   // x @ W
__device__ float g_p1[NMAX];               // x . w_pred[:128]
__device__ float g_p2[NMAX];               // x . w_pred[128:]
__device__ float g_deg[NMAX];              // weighted in-degree (init 1 self loop)
__device__ float g_dis[NMAX];              // deg^{-1/2}
__device__ float g_ew[EMAX];               // sigmoid edge weights
__device__ int   g_cnt[NMAX];              // integer in-degree (edges only)
__device__ int   g_rowstart[NMAX + 1];     // CSR row offsets (by target)
__device__ int   g_cursor[NMAX];           // fill cursors
__device__ int   g_eidx[EMAX];             // edge ids bucketed by target

// ---------------------------------------------------------------------------
// K1: per-node dot products vs the two halves of w_pred; init deg/cnt.
// ---------------------------------------------------------------------------
__global__ void k_precompute(const float* __restrict__ x,
                             const float* __restrict__ wp, int n) {
    int warp = (blockIdx.x * blockDim.x + threadIdx.x) >> 5;
    int lane = threadIdx.x & 31;
    if (warp >= n) return;
    float4 xv = ((const float4*)(x + (size_t)warp * D))[lane];
    float4 w1 = ((const float4*)wp)[lane];
    float4 w2 = ((const float4*)(wp + D))[lane];
    float s1 = xv.x * w1.x + xv.y * w1.y + xv.z * w1.z + xv.w * w1.w;
    float s2 = xv.x * w2.x + xv.y * w2.y + xv.z * w2.z + xv.w * w2.w;
#pragma unroll
    for (int o = 16; o > 0; o >>= 1) {
        s1 += __shfl_xor_sync(0xffffffffu, s1, o);
        s2 += __shfl_xor_sync(0xffffffffu, s2, o);
    }
    if (lane == 0) {
        g_p1[warp] = s1;
        g_p2[warp] = s2;
        g_deg[warp] = 1.0f;
        g_cnt[warp] = 0;
    }
}

// ---------------------------------------------------------------------------
// K2: edge weights (sigmoid) + weighted degree + integer counts.
// ---------------------------------------------------------------------------
__global__ void k_edge(const int* __restrict__ src, const int* __restrict__ tgt,
                       const float* __restrict__ bp, int e) {
    int i = blockIdx.x * blockDim.x + threadIdx.x;
    if (i >= e) return;
    int s = src[i], t = tgt[i];
    float z = g_p1[s] + g_p2[t] + bp[0];
    float w = __fdividef(1.0f, 1.0f + __expf(-z));
    g_ew[i] = w;
    atomicAdd(&g_deg[t], w);
    atomicAdd(&g_cnt[t], 1);
}

// ---------------------------------------------------------------------------
// K3: single-block exclusive scan of counts -> rowstart/cursor; dis=rsqrt(deg).
// ---------------------------------------------------------------------------
__global__ void k_scan(int n) {
    __shared__ int ssum[1024];
    int tid = threadIdx.x;
    int chunk = (n + 1023) >> 10;
    int lo = tid * chunk;
    int hi = min(n, lo + chunk);
    int s = 0;
    for (int j = lo; j < hi; j++) s += g_cnt[j];
    ssum[tid] = s;
    __syncthreads();
    for (int off = 1; off < 1024; off <<= 1) {
        int v = (tid >= off) ? ssum[tid - off] : 0;
        __syncthreads();
        ssum[tid] += v;
        __syncthreads();
    }
    int run = ssum[tid] - s;  // exclusive prefix
    for (int j = lo; j < hi; j++) {
        g_rowstart[j] = run;
        g_cursor[j] = run;
        run += g_cnt[j];
        float dg = g_deg[j];
        g_dis[j] = (dg > 0.f) ? rsqrtf(dg) : 0.f;
    }
    if (tid == 0) g_rowstart[n] = ssum[1023];
}

// ---------------------------------------------------------------------------
// K4: bucket edge ids by target (CSR fill).
// ---------------------------------------------------------------------------
__global__ void k_fill(const int* __restrict__ tgt, int e) {
    int i = blockIdx.x * blockDim.x + threadIdx.x;
    if (i >= e) return;
    int pos = atomicAdd(&g_cursor[tgt[i]], 1);
    g_eidx[pos] = i;
}

// ---------------------------------------------------------------------------
// K5: xw = x @ W via 3xTF32 tensor-core MMA (hi*hi + hi*lo + lo*hi).
// 128x128 block tile, 256 threads; warp w: rows 16w..16w+15, all 128 cols.
// ---------------------------------------------------------------------------
__device__ __forceinline__ void tf32_split(float v, unsigned& hi, unsigned& lo) {
    unsigned h;
    asm("cvt.rna.tf32.f32 %0, %1;" : "=r"(h) : "f"(v));
    float lf = v - __uint_as_float(h);
    unsigned l;
    asm("cvt.rna.tf32.f32 %0, %1;" : "=r"(l) : "f"(lf));
    hi = h; lo = l;
}

__device__ __forceinline__ void mma_tf32(float* c, const unsigned* a,
                                         unsigned b0, unsigned b1) {
    asm volatile(
        "mma.sync.aligned.m16n8k8.row.col.f32.tf32.tf32.f32 "
        "{%0,%1,%2,%3}, {%4,%5,%6,%7}, {%8,%9}, {%0,%1,%2,%3};"
        : "+f"(c[0]), "+f"(c[1]), "+f"(c[2]), "+f"(c[3])
        : "r"(a[0]), "r"(a[1]), "r"(a[2]), "r"(a[3]), "r"(b0), "r"(b1));
}

__global__ void k_gemm_tc(const float* __restrict__ x,
                          const float* __restrict__ W, int n) {
    extern __shared__ float sh[];
    float* Xs = sh;               // [128][GPAD]
    float* Ws = sh + 128 * GPAD;  // [k][GPAD]
    int tid = threadIdx.x;
    int warp = tid >> 5;
    int lane = tid & 31;
    int row0 = blockIdx.x * 128;

    for (int i = tid; i < 128 * 32; i += 256) {
        int r = i >> 5, c4 = i & 31;
        *(float4*)&Ws[r * GPAD + c4 * 4] = ((const float4*)W)[i];
        int gr = row0 + r;
        float4 v = make_float4(0.f, 0.f, 0.f, 0.f);
        if (gr < n) v = ((const float4*)x)[(size_t)gr * 32 + c4];
        *(float4*)&Xs[r * GPAD + c4 * 4] = v;
    }
    __syncthreads();

    float acc[16][4];
#pragma unroll
    for (int t = 0; t < 16; t++)
#pragma unroll
        for (int j = 0; j < 4; j++) acc[t][j] = 0.f;

    int arow = warp * 16 + (lane >> 2);
    int acol = lane & 3;
    int bq = lane >> 2;

#pragma unroll 1
    for (int ks = 0; ks < 16; ks++) {
        int k0 = ks * 8;
        unsigned ahi[4], alo[4];
        tf32_split(Xs[arow * GPAD + k0 + acol],           ahi[0], alo[0]);
        tf32_split(Xs[(arow + 8) * GPAD + k0 + acol],     ahi[1], alo[1]);
        tf32_split(Xs[arow * GPAD + k0 + acol + 4],       ahi[2], alo[2]);
        tf32_split(Xs[(arow + 8) * GPAD + k0 + acol + 4], ahi[3], alo[3]);
#pragma unroll
        for (int nt = 0; nt < 16; nt++) {
            unsigned bh0, bl0, bh1, bl1;
            tf32_split(Ws[(k0 + acol) * GPAD + nt * 8 + bq],     bh0, bl0);
            tf32_split(Ws[(k0 + acol + 4) * GPAD + nt * 8 + bq], bh1, bl1);
            mma_tf32(acc[nt], ahi, bh0, bh1);
            mma_tf32(acc[nt], ahi, bl0, bl1);
            mma_tf32(acc[nt], alo, bh0, bh1);
        }
    }

    int orow = row0 + arow;
    int oc = 2 * (lane & 3);
#pragma unroll
    for (int nt = 0; nt < 16; nt++) {
        if (orow < n)
            *(float2*)&g_xw[(size_t)orow * D + nt * 8 + oc] =
                make_float2(acc[nt][0], acc[nt][1]);
        if (orow + 8 < n)
            *(float2*)&g_xw[(size_t)(orow + 8) * D + nt * 8 + oc] =
                make_float2(acc[nt][2], acc[nt][3]);
    }
}

// ---------------------------------------------------------------------------
// K6: atomic-free aggregation. Warp per target node: self term + bias, then
// gather L2-resident xw[src] rows along the CSR edge list; write row once.
// ---------------------------------------------------------------------------
__global__ void k_aggregate(const int* __restrict__ src,
                            const float* __restrict__ b,
                            float* __restrict__ out, int n) {
    int t = (blockIdx.x * blockDim.x + threadIdx.x) >> 5;
    int lane = threadIdx.x & 31;
    if (t >= n) return;
    float dt = g_dis[t];
    float4 xv = ((const float4*)g_xw)[(size_t)t * 32 + lane];
    float sc = dt * dt;
    float4 acc = make_float4(sc * xv.x, sc * xv.y, sc * xv.z, sc * xv.w);

    int p = g_rowstart[t];
    int p1 = g_rowstart[t + 1];
    int eid = (p < p1) ? g_eidx[p] : 0;
    while (p < p1) {
        int s = src[eid];
        float c = g_dis[s] * g_ew[eid] * dt;
        int eidn = (p + 1 < p1) ? g_eidx[p + 1] : 0;
        float4 v = ((const float4*)g_xw)[(size_t)s * 32 + lane];
        acc.x += c * v.x;
        acc.y += c * v.y;
        acc.z += c * v.z;
        acc.w += c * v.w;
        eid = eidn;
        p++;
    }
    float4 bv = ((const float4*)b)[lane];
    ((float4*)out)[(size_t)t * 32 + lane] =
        make_float4(acc.x + bv.x, acc.y + bv.y, acc.z + bv.z, acc.w + bv.w);
}

// ---------------------------------------------------------------------------
extern "C" void kernel_launch(void* const* d_in, const int* in_sizes, int n_in,
                              void* d_out, int out_size) {
    const float* x  = (const float*)d_in[0];
    const int*   ei = (const int*)d_in[1];
    const float* W  = (const float*)d_in[2];
    const float* b  = (const float*)d_in[3];
    const float* wp = (const float*)d_in[4];
    const float* bp = (const float*)d_in[5];
    float* out = (float*)d_out;

    int n = in_sizes[0] / D;
    int e = in_sizes[1] / 2;
    const int* src = ei;
    const int* tgt = ei + e;

    int smem = 2 * 128 * GPAD * (int)sizeof(float);  // 136 KB
    cudaFuncSetAttribute(k_gemm_tc, cudaFuncAttributeMaxDynamicSharedMemorySize,
                         smem);

    k_precompute<<<(n + 7) / 8, 256>>>(x, wp, n);
    k_edge<<<(e + 255) / 256, 256>>>(src, tgt, bp, e);
    k_scan<<<1, 1024>>>(n);
    k_fill<<<(e + 255) / 256, 256>>>(tgt, e);
    k_gemm_tc<<<(n + 127) / 128, 256, smem>>>(x, W, n);
    k_aggregate<<<(n * 32 + 255) / 256, 256>>>(src, b, out, n);
}

// round 4
// speedup vs baseline: 1.5860x; 1.5860x over previous
#include <cuda_runtime.h>
#include <math.h>

#define D 128
#define NMAX 50000
#define EMAX 800000
#define BM 64

// Scratch (device globals — no allocation allowed in kernel_launch)
__device__ float g_xw[(size_t)NMAX * D];   // x @ W
__device__ float g_p1[NMAX];               // x . w_pred[:128]
__device__ float g_p2[NMAX];               // x . w_pred[128:]
__device__ float g_deg[NMAX];              // weighted in-degree (init 1 self loop)
__device__ float g_dis[NMAX];              // deg^{-1/2}
__device__ float g_ew[EMAX];               // sigmoid edge weights

// ---------------------------------------------------------------------------
// K1: per-node dot products with the two halves of w_pred; init deg=1.
// ---------------------------------------------------------------------------
__global__ void k_precompute(const float* __restrict__ x,
                             const float* __restrict__ wp, int n) {
    int warp = (blockIdx.x * blockDim.x + threadIdx.x) >> 5;
    int lane = threadIdx.x & 31;
    if (warp >= n) return;
    float4 xv = ((const float4*)(x + (size_t)warp * D))[lane];
    float4 w1 = ((const float4*)wp)[lane];
    float4 w2 = ((const float4*)(wp + D))[lane];
    float s1 = xv.x * w1.x + xv.y * w1.y + xv.z * w1.z + xv.w * w1.w;
    float s2 = xv.x * w2.x + xv.y * w2.y + xv.z * w2.z + xv.w * w2.w;
#pragma unroll
    for (int o = 16; o > 0; o >>= 1) {
        s1 += __shfl_xor_sync(0xffffffffu, s1, o);
        s2 += __shfl_xor_sync(0xffffffffu, s2, o);
    }
    if (lane == 0) {
        g_p1[warp] = s1;
        g_p2[warp] = s2;
        g_deg[warp] = 1.0f;
    }
}

// ---------------------------------------------------------------------------
// K2: edge weights (sigmoid) + weighted in-degree via atomics.
// ---------------------------------------------------------------------------
__global__ void k_edge(const int* __restrict__ src, const int* __restrict__ tgt,
                       const float* __restrict__ bp, int e) {
    int i = blockIdx.x * blockDim.x + threadIdx.x;
    if (i >= e) return;
    int s = src[i], t = tgt[i];
    float z = g_p1[s] + g_p2[t] + bp[0];
    float w = __fdividef(1.0f, 1.0f + __expf(-z));
    g_ew[i] = w;
    atomicAdd(&g_deg[t], w);
}

// ---------------------------------------------------------------------------
// K3: xw = x @ W with packed FFMA2 (fma.rn.f32x2) — 2 fp32 FMAs per issue.
// W (64KB) + 64-row X tile (32KB) in smem; 256 threads; thread = 8 rows x 4
// cols. Per k per thread: 8 broadcast LDS + 1 LDS.128 + 8 pack-movs (ALU pipe)
// + 16 FFMA2 (FMA pipe) -> FMA-bound at half the R2 issue count.
// ---------------------------------------------------------------------------
__global__ void k_gemm(const float* __restrict__ x, const float* __restrict__ W,
                       int n) {
    extern __shared__ float sh[];
    float* Ws = sh;            // [k][j]  128*128
    float* Xs = sh + D * D;    // [r][k]  BM*128
    int tid = threadIdx.x;
    int row0 = blockIdx.x * BM;

    for (int i = tid; i < D * D / 4; i += 256)
        ((float4*)Ws)[i] = ((const float4*)W)[i];
    for (int i = tid; i < BM * D / 4; i += 256) {
        int r = i >> 5;
        int gr = row0 + r;
        float4 v = make_float4(0.f, 0.f, 0.f, 0.f);
        if (gr < n) v = ((const float4*)x)[(size_t)gr * 32 + (i & 31)];
        ((float4*)Xs)[i] = v;
    }
    __syncthreads();

    int tcol = tid & 31;   // cols tcol*4 .. +3 (LDS.128, conflict-free)
    int trow = tid >> 5;   // rows trow*8 .. +7 (broadcast loads)

    unsigned long long acc[8][2];  // [row][pair]: (c0,c1),(c2,c3) packed fp32x2
#pragma unroll
    for (int i = 0; i < 8; i++) {
        acc[i][0] = 0ull;
        acc[i][1] = 0ull;
    }

#pragma unroll 4
    for (int k = 0; k < D; k++) {
        float4 bv = *((const float4*)&Ws[k * D + tcol * 4]);
        unsigned long long b01, b23;
        asm("mov.b64 %0, {%1, %2};" : "=l"(b01) : "f"(bv.x), "f"(bv.y));
        asm("mov.b64 %0, {%1, %2};" : "=l"(b23) : "f"(bv.z), "f"(bv.w));
#pragma unroll
        for (int i = 0; i < 8; i++) {
            float a = Xs[(trow * 8 + i) * D + k];
            unsigned long long aa;
            asm("mov.b64 %0, {%1, %1};" : "=l"(aa) : "f"(a));
            asm("fma.rn.f32x2 %0, %1, %2, %0;" : "+l"(acc[i][0])
                : "l"(aa), "l"(b01));
            asm("fma.rn.f32x2 %0, %1, %2, %0;" : "+l"(acc[i][1])
                : "l"(aa), "l"(b23));
        }
    }

#pragma unroll
    for (int i = 0; i < 8; i++) {
        int gr = row0 + trow * 8 + i;
        if (gr < n) {
            float c0, c1, c2, c3;
            asm("mov.b64 {%0, %1}, %2;" : "=f"(c0), "=f"(c1) : "l"(acc[i][0]));
            asm("mov.b64 {%0, %1}, %2;" : "=f"(c2), "=f"(c3) : "l"(acc[i][1]));
            *((float4*)&g_xw[(size_t)gr * D + tcol * 4]) =
                make_float4(c0, c1, c2, c3);
        }
    }
}

// ---------------------------------------------------------------------------
// K4: dis = rsqrt(deg); out = b + dis^2 * xw (self loop + bias; initializes
// the poisoned output buffer).
// ---------------------------------------------------------------------------
__global__ void k_selfinit(const float* __restrict__ b, float* __restrict__ out,
                           int n) {
    int i = blockIdx.x * blockDim.x + threadIdx.x;
    if (i >= n * 32) return;
    int node = i >> 5;
    int c4 = i & 31;
    float dg = g_deg[node];
    float ds = (dg > 0.f) ? rsqrtf(dg) : 0.f;
    float sc = ds * ds;
    float4 xv = ((const float4*)g_xw)[i];
    float4 bv = ((const float4*)b)[c4];
    ((float4*)out)[i] = make_float4(bv.x + sc * xv.x, bv.y + sc * xv.y,
                                    bv.z + sc * xv.z, bv.w + sc * xv.w);
    if (c4 == 0) g_dis[node] = ds;
}

// ---------------------------------------------------------------------------
// K5: edge scatter. Warp per edge: gather xw[src] (L2-resident), scale,
// one red.global.add.v4.f32 per lane.
// ---------------------------------------------------------------------------
__global__ void k_scatter(const int* __restrict__ src, const int* __restrict__ tgt,
                          float* __restrict__ out, int e) {
    int w = (blockIdx.x * blockDim.x + threadIdx.x) >> 5;
    int lane = threadIdx.x & 31;
    if (w >= e) return;
    int s = src[w], t = tgt[w];
    float c = g_dis[s] * g_ew[w] * g_dis[t];
    float4 v = ((const float4*)g_xw)[(size_t)s * 32 + lane];
    float* o = out + (size_t)t * D + lane * 4;
    asm volatile("red.global.add.v4.f32 [%0], {%1, %2, %3, %4};"
                 :: "l"(o), "f"(c * v.x), "f"(c * v.y), "f"(c * v.z),
                    "f"(c * v.w)
                 : "memory");
}

// ---------------------------------------------------------------------------
extern "C" void kernel_launch(void* const* d_in, const int* in_sizes, int n_in,
                              void* d_out, int out_size) {
    const float* x  = (const float*)d_in[0];
    const int*   ei = (const int*)d_in[1];
    const float* W  = (const float*)d_in[2];
    const float* b  = (const float*)d_in[3];
    const float* wp = (const float*)d_in[4];
    const float* bp = (const float*)d_in[5];
    float* out = (float*)d_out;

    int n = in_sizes[0] / D;
    int e = in_sizes[1] / 2;
    const int* src = ei;
    const int* tgt = ei + e;

    int smem = (D * D + BM * D) * (int)sizeof(float);  // 96 KB
    cudaFuncSetAttribute(k_gemm, cudaFuncAttributeMaxDynamicSharedMemorySize, smem);

    k_precompute<<<(n + 7) / 8, 256>>>(x, wp, n);
    k_edge<<<(e + 255) / 256, 256>>>(src, tgt, bp, e);
    k_gemm<<<(n + BM - 1) / BM, 256, smem>>>(x, W, n);
    k_selfinit<<<(n * 32 + 255) / 256, 256>>>(b, out, n);
    k_scatter<<<(e * 32 + 255) / 256, 256>>>(src, tgt, out, e);
}